// round 1
// baseline (speedup 1.0000x reference)
#include <cuda_runtime.h>

// Conv3DMod: out[b,oc,h,w,d] = demod[b,oc] * sum_{ic,kh,kw,kd} W[oc,ic,kh,kw,kd] * (y[b,ic]*x[b,ic,h+kh-1,w+kw-1,d+kd-1])
// demod[b,oc] = rsqrt( sum_ic y[b,ic]^2 * sum_taps W[oc,ic,taps]^2 + 1e-8 )

#define BB   4
#define CC   128
#define SS   32
#define OCC  128
#define TAPS 27
#define EPSF 1e-8f

// conv tiling
#define TH   8
#define TW   8
#define TD   16
#define OC_T 8
#define IC_T 4
#define HH   10
#define HW   10
#define HD   18

__device__ float g_demod[BB * OCC];

// ---------------------------------------------------------------------------
// demod: one block per oc, 128 threads (one per ic)
// ---------------------------------------------------------------------------
__global__ void demod_kernel(const float* __restrict__ y,
                             const float* __restrict__ w) {
    int oc = blockIdx.x;
    int ic = threadIdx.x;
    const float* wp = w + (oc * CC + ic) * TAPS;
    float wsum = 0.f;
#pragma unroll
    for (int t = 0; t < TAPS; t++) {
        float v = wp[t];
        wsum += v * v;
    }
    __shared__ float red[CC];
    for (int b = 0; b < BB; b++) {
        float yv = y[b * CC + ic];
        red[ic] = wsum * yv * yv;
        __syncthreads();
        for (int s = CC / 2; s > 0; s >>= 1) {
            if (ic < s) red[ic] += red[ic + s];
            __syncthreads();
        }
        if (ic == 0) g_demod[b * OCC + oc] = rsqrtf(red[0] + EPSF);
        __syncthreads();
    }
}

// ---------------------------------------------------------------------------
// direct conv, smem-tiled.
// Block: 256 threads. Output tile: TH x TW x TD spatial, OC_T channels.
// Each thread: 4 contiguous d-voxels, OC_T oc accumulators (32 regs).
// Inner structure: per (icl,kh,kw) load 6-float z-column into regs (reused
// across the 3 kd taps) + 24 broadcast weights -> 96 FMA per 30 smem floats.
// ---------------------------------------------------------------------------
__global__ __launch_bounds__(256) void conv_kernel(
    const float* __restrict__ x, const float* __restrict__ y,
    const float* __restrict__ w, float* __restrict__ out) {
    __shared__ float xs[IC_T][HH][HW][HD];
    __shared__ float wsm[IC_T][TAPS][OC_T];

    int t  = blockIdx.x;                 // 32 spatial tiles
    int d0 = (t & 1) * TD;
    int w0 = ((t >> 1) & 3) * TW;
    int h0 = (t >> 3) * TH;
    int oc0 = blockIdx.y * OC_T;
    int b   = blockIdx.z;

    int tid = threadIdx.x;
    int dg  = tid & 3;                   // d group (4 voxels each)
    int wq  = (tid >> 2) & 7;
    int hq  = tid >> 5;
    int db  = dg * 4;

    float acc[OC_T][4];
#pragma unroll
    for (int o = 0; o < OC_T; o++)
#pragma unroll
        for (int j = 0; j < 4; j++) acc[o][j] = 0.f;

    for (int ic0 = 0; ic0 < CC; ic0 += IC_T) {
        __syncthreads();
        // ---- load x tile (with halo), folding in y[b,ic] ----
        for (int e = tid; e < IC_T * HH * HW * HD; e += 256) {
            int icl = e / (HH * HW * HD);
            int r   = e % (HH * HW * HD);
            int hh  = r / (HW * HD);
            int r2  = r % (HW * HD);
            int ww  = r2 / HD;
            int dd  = r2 % HD;
            int gh = h0 + hh - 1, gw = w0 + ww - 1, gd = d0 + dd - 1;
            float v = 0.f;
            if ((unsigned)gh < SS && (unsigned)gw < SS && (unsigned)gd < SS) {
                int ic = ic0 + icl;
                v = x[((b * CC + ic) * SS + gh) * (SS * SS) + gw * SS + gd] *
                    y[b * CC + ic];
            }
            xs[icl][hh][ww][dd] = v;
        }
        // ---- load weight slice, transposed to [icl][tap][oc] ----
        for (int e = tid; e < IC_T * TAPS * OC_T; e += 256) {
            int icl = e / (TAPS * OC_T);
            int r   = e % (TAPS * OC_T);
            int tap = r / OC_T;
            int o   = r % OC_T;
            wsm[icl][tap][o] = w[((oc0 + o) * CC + (ic0 + icl)) * TAPS + tap];
        }
        __syncthreads();

        // ---- compute ----
#pragma unroll
        for (int icl = 0; icl < IC_T; icl++) {
#pragma unroll
            for (int kh = 0; kh < 3; kh++) {
#pragma unroll
                for (int kw = 0; kw < 3; kw++) {
                    float xv[6];
                    const float* xp = &xs[icl][hq + kh][wq + kw][db];
#pragma unroll
                    for (int tt = 0; tt < 6; tt++) xv[tt] = xp[tt];
#pragma unroll
                    for (int kd = 0; kd < 3; kd++) {
                        const float* wp = &wsm[icl][(kh * 3 + kw) * 3 + kd][0];
#pragma unroll
                        for (int o = 0; o < OC_T; o++) {
                            float wv = wp[o];
#pragma unroll
                            for (int j = 0; j < 4; j++)
                                acc[o][j] += wv * xv[j + kd];
                        }
                    }
                }
            }
        }
    }

    // ---- epilogue: scale by demod, vectorized float4 store ----
#pragma unroll
    for (int o = 0; o < OC_T; o++) {
        float dm = g_demod[b * OCC + oc0 + o];
        float4 v;
        v.x = acc[o][0] * dm;
        v.y = acc[o][1] * dm;
        v.z = acc[o][2] * dm;
        v.w = acc[o][3] * dm;
        float* op = out + ((b * OCC + oc0 + o) * SS + (h0 + hq)) * (SS * SS) +
                    (w0 + wq) * SS + (d0 + db);
        *reinterpret_cast<float4*>(op) = v;
    }
}

// ---------------------------------------------------------------------------
extern "C" void kernel_launch(void* const* d_in, const int* in_sizes, int n_in,
                              void* d_out, int out_size) {
    const float* x = (const float*)d_in[0];
    const float* y = (const float*)d_in[1];
    const float* w = (const float*)d_in[2];
    float* out = (float*)d_out;

    demod_kernel<<<OCC, CC>>>(y, w);

    dim3 grid(32, OCC / OC_T, BB);
    conv_kernel<<<grid, 256>>>(x, y, w, out);
}

// round 2
// speedup vs baseline: 1.1646x; 1.1646x over previous
#include <cuda_runtime.h>

// Conv3DMod via y-folded weights + fp32x2 packed FMA.
// out[b,oc,s] = demod[b,oc] * sum_{ic,taps} (W[oc,ic,tap]*y[b,ic]) * x[b,ic,shift(s,tap)]
// demod[b,oc] = rsqrt( sum_ic y[b,ic]^2 * sum_taps W^2 + 1e-8 )

#define BB   4
#define CC   128
#define SS   32
#define OCC  128
#define TAPS 27
#define EPSF 1e-8f

#define TH   8
#define TW   8
#define TD   16
#define OC_T 8
#define IC_T 4
#define HH   10
#define HW   10
#define HD   18
#define NTHR 128

__device__ float g_demod[BB * OCC];

// ---------------------------------------------------------------------------
// f32x2 helpers (sm_100+ packed fp32 pipe)
// ---------------------------------------------------------------------------
__device__ __forceinline__ unsigned long long ffma2(unsigned long long a,
                                                    unsigned long long b,
                                                    unsigned long long c) {
    unsigned long long d;
    asm("fma.rn.f32x2 %0, %1, %2, %3;" : "=l"(d) : "l"(a), "l"(b), "l"(c));
    return d;
}
__device__ __forceinline__ unsigned long long pack2(float lo, float hi) {
    unsigned long long r;
    asm("mov.b64 %0, {%1, %2};" : "=l"(r) : "f"(lo), "f"(hi));
    return r;
}
__device__ __forceinline__ void unpack2(unsigned long long v, float& lo, float& hi) {
    asm("mov.b64 {%0, %1}, %2;" : "=f"(lo), "=f"(hi) : "l"(v));
}

// ---------------------------------------------------------------------------
// demod: one block per oc, 128 threads (one per ic)
// ---------------------------------------------------------------------------
__global__ void demod_kernel(const float* __restrict__ y,
                             const float* __restrict__ w) {
    int oc = blockIdx.x;
    int ic = threadIdx.x;
    const float* wp = w + (oc * CC + ic) * TAPS;
    float wsum = 0.f;
#pragma unroll
    for (int t = 0; t < TAPS; t++) {
        float v = wp[t];
        wsum += v * v;
    }
    __shared__ float red[CC];
    for (int b = 0; b < BB; b++) {
        float yv = y[b * CC + ic];
        red[ic] = wsum * yv * yv;
        __syncthreads();
        for (int s = CC / 2; s > 0; s >>= 1) {
            if (ic < s) red[ic] += red[ic + s];
            __syncthreads();
        }
        if (ic == 0) g_demod[b * OCC + oc] = rsqrtf(red[0] + EPSF);
        __syncthreads();
    }
}

// ---------------------------------------------------------------------------
// conv kernel: 128 threads, tile TH x TW x TD, OC_T oc.
// thread: 8 contiguous d-voxels, OC_T oc -> acc = 8x4 f32x2.
// ---------------------------------------------------------------------------
__global__ __launch_bounds__(NTHR, 4) void conv_kernel(
    const float* __restrict__ x, const float* __restrict__ y,
    const float* __restrict__ w, float* __restrict__ out) {
    __shared__ float  xs[IC_T][HH][HW][HD];
    __shared__ float2 wsm[IC_T][TAPS][OC_T];   // duplicated {w*y, w*y}

    int t  = blockIdx.x;                 // 32 spatial tiles
    int d0 = (t & 1) * TD;
    int w0 = ((t >> 1) & 3) * TW;
    int h0 = (t >> 3) * TH;
    int oc0 = blockIdx.y * OC_T;
    int b   = blockIdx.z;

    int tid = threadIdx.x;
    int dg  = tid & 1;                   // d half (8 voxels each)
    int wq  = (tid >> 1) & 7;
    int hq  = tid >> 4;
    int db  = dg * 8;

    unsigned long long acc[OC_T][4];
#pragma unroll
    for (int o = 0; o < OC_T; o++)
#pragma unroll
        for (int j = 0; j < 4; j++) acc[o][j] = 0ull;

    for (int ic0 = 0; ic0 < CC; ic0 += IC_T) {
        __syncthreads();
        // ---- x loader: 400 rows of 18 floats (raw x, no y fold) ----
        for (int r = tid; r < IC_T * HH * HW; r += NTHR) {
            int icl = r / (HH * HW);
            int rr  = r % (HH * HW);
            int hh  = rr / HW;
            int ww  = rr % HW;
            int gh = h0 + hh - 1, gw = w0 + ww - 1;
            float* dst = &xs[icl][hh][ww][0];
            if ((unsigned)gh < SS && (unsigned)gw < SS) {
                const float* src =
                    x + ((size_t)((b * CC + ic0 + icl) * SS + gh) * SS + gw) * SS;
                // left halo
                dst[0] = (d0 > 0) ? src[d0 - 1] : 0.f;
                // interior: 16 floats, 4x float4 (aligned: d0 % 16 == 0)
#pragma unroll
                for (int q = 0; q < 4; q++) {
                    float4 v = *reinterpret_cast<const float4*>(src + d0 + q * 4);
                    dst[1 + q * 4 + 0] = v.x;
                    dst[1 + q * 4 + 1] = v.y;
                    dst[1 + q * 4 + 2] = v.z;
                    dst[1 + q * 4 + 3] = v.w;
                }
                // right halo
                dst[17] = (d0 + 16 < SS) ? src[d0 + 16] : 0.f;
            } else {
#pragma unroll
                for (int i = 0; i < HD; i++) dst[i] = 0.f;
            }
        }
        // ---- weight loader: fold y, duplicate for f32x2 ----
        for (int e = tid; e < IC_T * TAPS * OC_T; e += NTHR) {
            int icl = e / (TAPS * OC_T);
            int rr  = e % (TAPS * OC_T);
            int tap = rr / OC_T;
            int o   = rr % OC_T;
            float v = w[((oc0 + o) * CC + (ic0 + icl)) * TAPS + tap] *
                      y[b * CC + ic0 + icl];
            wsm[icl][tap][o] = make_float2(v, v);
        }
        __syncthreads();

        // ---- compute ----
#pragma unroll 1
        for (int icl = 0; icl < IC_T; icl++) {
#pragma unroll
            for (int kh = 0; kh < 3; kh++) {
#pragma unroll
                for (int kw = 0; kw < 3; kw++) {
                    const float2* xp = reinterpret_cast<const float2*>(
                        &xs[icl][hq + kh][wq + kw][db]);
                    float2 xq[5];
#pragma unroll
                    for (int i = 0; i < 5; i++) xq[i] = xp[i];
                    // kd=0 pairs: xq[0..3]; kd=2 pairs: xq[1..4];
                    // kd=1 pairs: pack(xq[p].y, xq[p+1].x)
                    unsigned long long p0[4], p1[4], p2[4];
#pragma unroll
                    for (int p = 0; p < 4; p++) {
                        p0[p] = pack2(xq[p].x, xq[p].y);
                        p2[p] = pack2(xq[p + 1].x, xq[p + 1].y);
                        p1[p] = pack2(xq[p].y, xq[p + 1].x);
                    }
                    const unsigned long long* wp =
                        reinterpret_cast<const unsigned long long*>(
                            &wsm[icl][(kh * 3 + kw) * 3][0]);
                    // kd = 0
#pragma unroll
                    for (int o = 0; o < OC_T; o++) {
                        unsigned long long wv = wp[o];
#pragma unroll
                        for (int p = 0; p < 4; p++)
                            acc[o][p] = ffma2(wv, p0[p], acc[o][p]);
                    }
                    // kd = 1
#pragma unroll
                    for (int o = 0; o < OC_T; o++) {
                        unsigned long long wv = wp[OC_T + o];
#pragma unroll
                        for (int p = 0; p < 4; p++)
                            acc[o][p] = ffma2(wv, p1[p], acc[o][p]);
                    }
                    // kd = 2
#pragma unroll
                    for (int o = 0; o < OC_T; o++) {
                        unsigned long long wv = wp[2 * OC_T + o];
#pragma unroll
                        for (int p = 0; p < 4; p++)
                            acc[o][p] = ffma2(wv, p2[p], acc[o][p]);
                    }
                }
            }
        }
    }

    // ---- epilogue: demod scale, two float4 stores per oc ----
#pragma unroll
    for (int o = 0; o < OC_T; o++) {
        float dm = g_demod[b * OCC + oc0 + o];
        float v[8];
#pragma unroll
        for (int p = 0; p < 4; p++) {
            unpack2(acc[o][p], v[2 * p], v[2 * p + 1]);
            v[2 * p]     *= dm;
            v[2 * p + 1] *= dm;
        }
        float* op = out + ((size_t)((b * OCC + oc0 + o) * SS + (h0 + hq)) * SS +
                           (w0 + wq)) * SS + (d0 + db);
        *reinterpret_cast<float4*>(op)     = make_float4(v[0], v[1], v[2], v[3]);
        *reinterpret_cast<float4*>(op + 4) = make_float4(v[4], v[5], v[6], v[7]);
    }
}

// ---------------------------------------------------------------------------
extern "C" void kernel_launch(void* const* d_in, const int* in_sizes, int n_in,
                              void* d_out, int out_size) {
    const float* x = (const float*)d_in[0];
    const float* y = (const float*)d_in[1];
    const float* w = (const float*)d_in[2];
    float* out = (float*)d_out;

    demod_kernel<<<OCC, CC>>>(y, w);

    dim3 grid(32, OCC / OC_T, BB);
    conv_kernel<<<grid, NTHR>>>(x, y, w, out);
}

// round 3
// speedup vs baseline: 1.1647x; 1.0001x over previous
#include <cuda_runtime.h>

// Conv3DMod via y-folded weights + fp32x2 packed FMA.
// out[b,oc,s] = demod[b,oc] * sum_{ic,taps} (W[oc,ic,tap]*y[b,ic]) * x[b,ic,shift(s,tap)]
// demod[b,oc] = rsqrt( sum_ic y[b,ic]^2 * sum_taps W^2 + 1e-8 )

#define BB   4
#define CC   128
#define SS   32
#define OCC  128
#define TAPS 27
#define EPSF 1e-8f

#define TH   8
#define TW   8
#define TD   16
#define OC_T 8
#define IC_T 4
#define HH   10
#define HW   10
#define HD   18
#define NTHR 128

__device__ float g_demod[BB * OCC];

// ---------------------------------------------------------------------------
// f32x2 helpers (sm_100+ packed fp32 pipe)
// ---------------------------------------------------------------------------
__device__ __forceinline__ unsigned long long ffma2(unsigned long long a,
                                                    unsigned long long b,
                                                    unsigned long long c) {
    unsigned long long d;
    asm("fma.rn.f32x2 %0, %1, %2, %3;" : "=l"(d) : "l"(a), "l"(b), "l"(c));
    return d;
}
__device__ __forceinline__ unsigned long long pack2(float lo, float hi) {
    unsigned long long r;
    asm("mov.b64 %0, {%1, %2};" : "=l"(r) : "f"(lo), "f"(hi));
    return r;
}
__device__ __forceinline__ void unpack2(unsigned long long v, float& lo, float& hi) {
    asm("mov.b64 {%0, %1}, %2;" : "=f"(lo), "=f"(hi) : "l"(v));
}

// ---------------------------------------------------------------------------
// demod: one block per oc, 128 threads (one per ic)
// ---------------------------------------------------------------------------
__global__ void demod_kernel(const float* __restrict__ y,
                             const float* __restrict__ w) {
    int oc = blockIdx.x;
    int ic = threadIdx.x;
    const float* wp = w + (oc * CC + ic) * TAPS;
    float wsum = 0.f;
#pragma unroll
    for (int t = 0; t < TAPS; t++) {
        float v = wp[t];
        wsum += v * v;
    }
    __shared__ float red[CC];
    for (int b = 0; b < BB; b++) {
        float yv = y[b * CC + ic];
        red[ic] = wsum * yv * yv;
        __syncthreads();
        for (int s = CC / 2; s > 0; s >>= 1) {
            if (ic < s) red[ic] += red[ic + s];
            __syncthreads();
        }
        if (ic == 0) g_demod[b * OCC + oc] = rsqrtf(red[0] + EPSF);
        __syncthreads();
    }
}

// ---------------------------------------------------------------------------
// conv kernel: 128 threads, tile TH x TW x TD, OC_T oc.
// thread: 8 contiguous d-voxels, OC_T oc -> acc = 8x4 f32x2.
// ---------------------------------------------------------------------------
__global__ __launch_bounds__(NTHR, 4) void conv_kernel(
    const float* __restrict__ x, const float* __restrict__ y,
    const float* __restrict__ w, float* __restrict__ out) {
    __shared__ float  xs[IC_T][HH][HW][HD];
    __shared__ float2 wsm[IC_T][TAPS][OC_T];   // duplicated {w*y, w*y}

    int t  = blockIdx.x;                 // 32 spatial tiles
    int d0 = (t & 1) * TD;
    int w0 = ((t >> 1) & 3) * TW;
    int h0 = (t >> 3) * TH;
    int oc0 = blockIdx.y * OC_T;
    int b   = blockIdx.z;

    int tid = threadIdx.x;
    int dg  = tid & 1;                   // d half (8 voxels each)
    int wq  = (tid >> 1) & 7;
    int hq  = tid >> 4;
    int db  = dg * 8;

    unsigned long long acc[OC_T][4];
#pragma unroll
    for (int o = 0; o < OC_T; o++)
#pragma unroll
        for (int j = 0; j < 4; j++) acc[o][j] = 0ull;

    for (int ic0 = 0; ic0 < CC; ic0 += IC_T) {
        __syncthreads();
        // ---- x loader: 400 rows of 18 floats (raw x, no y fold) ----
        for (int r = tid; r < IC_T * HH * HW; r += NTHR) {
            int icl = r / (HH * HW);
            int rr  = r % (HH * HW);
            int hh  = rr / HW;
            int ww  = rr % HW;
            int gh = h0 + hh - 1, gw = w0 + ww - 1;
            float* dst = &xs[icl][hh][ww][0];
            if ((unsigned)gh < SS && (unsigned)gw < SS) {
                const float* src =
                    x + ((size_t)((b * CC + ic0 + icl) * SS + gh) * SS + gw) * SS;
                // left halo
                dst[0] = (d0 > 0) ? src[d0 - 1] : 0.f;
                // interior: 16 floats, 4x float4 (aligned: d0 % 16 == 0)
#pragma unroll
                for (int q = 0; q < 4; q++) {
                    float4 v = *reinterpret_cast<const float4*>(src + d0 + q * 4);
                    dst[1 + q * 4 + 0] = v.x;
                    dst[1 + q * 4 + 1] = v.y;
                    dst[1 + q * 4 + 2] = v.z;
                    dst[1 + q * 4 + 3] = v.w;
                }
                // right halo
                dst[17] = (d0 + 16 < SS) ? src[d0 + 16] : 0.f;
            } else {
#pragma unroll
                for (int i = 0; i < HD; i++) dst[i] = 0.f;
            }
        }
        // ---- weight loader: fold y, duplicate for f32x2 ----
        for (int e = tid; e < IC_T * TAPS * OC_T; e += NTHR) {
            int icl = e / (TAPS * OC_T);
            int rr  = e % (TAPS * OC_T);
            int tap = rr / OC_T;
            int o   = rr % OC_T;
            float v = w[((oc0 + o) * CC + (ic0 + icl)) * TAPS + tap] *
                      y[b * CC + ic0 + icl];
            wsm[icl][tap][o] = make_float2(v, v);
        }
        __syncthreads();

        // ---- compute ----
#pragma unroll 1
        for (int icl = 0; icl < IC_T; icl++) {
#pragma unroll
            for (int kh = 0; kh < 3; kh++) {
#pragma unroll
                for (int kw = 0; kw < 3; kw++) {
                    const float2* xp = reinterpret_cast<const float2*>(
                        &xs[icl][hq + kh][wq + kw][db]);
                    float2 xq[5];
#pragma unroll
                    for (int i = 0; i < 5; i++) xq[i] = xp[i];
                    // kd=0 pairs: xq[0..3]; kd=2 pairs: xq[1..4];
                    // kd=1 pairs: pack(xq[p].y, xq[p+1].x)
                    unsigned long long p0[4], p1[4], p2[4];
#pragma unroll
                    for (int p = 0; p < 4; p++) {
                        p0[p] = pack2(xq[p].x, xq[p].y);
                        p2[p] = pack2(xq[p + 1].x, xq[p + 1].y);
                        p1[p] = pack2(xq[p].y, xq[p + 1].x);
                    }
                    const unsigned long long* wp =
                        reinterpret_cast<const unsigned long long*>(
                            &wsm[icl][(kh * 3 + kw) * 3][0]);
                    // kd = 0
#pragma unroll
                    for (int o = 0; o < OC_T; o++) {
                        unsigned long long wv = wp[o];
#pragma unroll
                        for (int p = 0; p < 4; p++)
                            acc[o][p] = ffma2(wv, p0[p], acc[o][p]);
                    }
                    // kd = 1
#pragma unroll
                    for (int o = 0; o < OC_T; o++) {
                        unsigned long long wv = wp[OC_T + o];
#pragma unroll
                        for (int p = 0; p < 4; p++)
                            acc[o][p] = ffma2(wv, p1[p], acc[o][p]);
                    }
                    // kd = 2
#pragma unroll
                    for (int o = 0; o < OC_T; o++) {
                        unsigned long long wv = wp[2 * OC_T + o];
#pragma unroll
                        for (int p = 0; p < 4; p++)
                            acc[o][p] = ffma2(wv, p2[p], acc[o][p]);
                    }
                }
            }
        }
    }

    // ---- epilogue: demod scale, two float4 stores per oc ----
#pragma unroll
    for (int o = 0; o < OC_T; o++) {
        float dm = g_demod[b * OCC + oc0 + o];
        float v[8];
#pragma unroll
        for (int p = 0; p < 4; p++) {
            unpack2(acc[o][p], v[2 * p], v[2 * p + 1]);
            v[2 * p]     *= dm;
            v[2 * p + 1] *= dm;
        }
        float* op = out + ((size_t)((b * OCC + oc0 + o) * SS + (h0 + hq)) * SS +
                           (w0 + wq)) * SS + (d0 + db);
        *reinterpret_cast<float4*>(op)     = make_float4(v[0], v[1], v[2], v[3]);
        *reinterpret_cast<float4*>(op + 4) = make_float4(v[4], v[5], v[6], v[7]);
    }
}

// ---------------------------------------------------------------------------
extern "C" void kernel_launch(void* const* d_in, const int* in_sizes, int n_in,
                              void* d_out, int out_size) {
    const float* x = (const float*)d_in[0];
    const float* y = (const float*)d_in[1];
    const float* w = (const float*)d_in[2];
    float* out = (float*)d_out;

    demod_kernel<<<OCC, CC>>>(y, w);

    dim3 grid(32, OCC / OC_T, BB);
    conv_kernel<<<grid, NTHR>>>(x, y, w, out);
}

// round 6
// speedup vs baseline: 3.4298x; 2.9449x over previous
#include <cuda_runtime.h>
#include <cuda_bf16.h>
#include <cstdint>
#include <cstddef>

#define BB   4
#define CC   128
#define SS   32
#define OCC  128
#define EPSF 1e-8f

#define NSTAGE 54            // 27 taps * 2 ic-halves
#define A_BYTES 16384        // 128 oc x 128B (64 ic bf16)
#define B_BYTES 32768        // 256 n  x 128B
#define B_OFF   (4 * A_BYTES)
#define SMEM_TOTAL (B_OFF + 4 * B_BYTES)   // 192 KB

__device__ float g_demod[BB * OCC];
__device__ __align__(256) __nv_bfloat16 g_whi[NSTAGE * 128 * 64];
__device__ __align__(256) __nv_bfloat16 g_wlo[NSTAGE * 128 * 64];
__device__ __align__(256) __nv_bfloat16 g_xhi[(size_t)BB * SS * SS * SS * CC];
__device__ __align__(256) __nv_bfloat16 g_xlo[(size_t)BB * SS * SS * SS * CC];

// ---------------- PTX helpers ----------------
__device__ __forceinline__ uint32_t smem_u32(const void* p) {
    uint32_t a;
    asm("{ .reg .u64 t; cvta.to.shared.u64 t, %1; cvt.u32.u64 %0, t; }" : "=r"(a) : "l"(p));
    return a;
}
__device__ __forceinline__ void cpasync16(uint32_t dst, const void* src, int sz) {
    asm volatile("cp.async.cg.shared.global [%0], [%1], 16, %2;"
                 :: "r"(dst), "l"(src), "r"(sz) : "memory");
}
#define CP_COMMIT() asm volatile("cp.async.commit_group;" ::: "memory")
#define CP_WAIT(n)  asm volatile("cp.async.wait_group %0;" :: "n"(n) : "memory")

__device__ __forceinline__ void ldsm4(uint32_t& r0, uint32_t& r1, uint32_t& r2,
                                      uint32_t& r3, uint32_t addr) {
    asm volatile("ldmatrix.sync.aligned.m8n8.x4.shared.b16 {%0,%1,%2,%3}, [%4];"
                 : "=r"(r0), "=r"(r1), "=r"(r2), "=r"(r3) : "r"(addr));
}
__device__ __forceinline__ void mma16816(float* c, const uint32_t* a, const uint32_t* b) {
    asm volatile(
        "mma.sync.aligned.m16n8k16.row.col.f32.bf16.bf16.f32 "
        "{%0,%1,%2,%3}, {%4,%5,%6,%7}, {%8,%9}, {%0,%1,%2,%3};"
        : "+f"(c[0]), "+f"(c[1]), "+f"(c[2]), "+f"(c[3])
        : "r"(a[0]), "r"(a[1]), "r"(a[2]), "r"(a[3]), "r"(b[0]), "r"(b[1]));
}
__device__ __forceinline__ uint32_t sw128(uint32_t off) { return off ^ ((off >> 3) & 0x70); }

// ---------------- prepass: demod ----------------
__global__ void demod_kernel(const float* __restrict__ y, const float* __restrict__ w) {
    int oc = blockIdx.x, ic = threadIdx.x;
    const float* wp = w + (oc * CC + ic) * 27;
    float wsum = 0.f;
#pragma unroll
    for (int t = 0; t < 27; t++) { float v = wp[t]; wsum += v * v; }
    __shared__ float red[CC];
    for (int b = 0; b < BB; b++) {
        float yv = y[b * CC + ic];
        red[ic] = wsum * yv * yv;
        __syncthreads();
        for (int s = CC / 2; s > 0; s >>= 1) {
            if (ic < s) red[ic] += red[ic + s];
            __syncthreads();
        }
        if (ic == 0) g_demod[b * OCC + oc] = rsqrtf(red[0] + EPSF);
        __syncthreads();
    }
}

// ---------------- prepass: weight hi/lo split, [stage][oc][icl] ----------------
__global__ void wsplit_kernel(const float* __restrict__ w) {
    int oc = blockIdx.x, ic = threadIdx.x;
    int ichalf = ic >> 6, icl = ic & 63;
#pragma unroll 1
    for (int t = 0; t < 27; t++) {
        float v = w[(oc * CC + ic) * 27 + t];
        __nv_bfloat16 hi = __float2bfloat16(v);
        __nv_bfloat16 lo = __float2bfloat16(v - __bfloat162float(hi));
        int st = t * 2 + ichalf;
        g_whi[(st * 128 + oc) * 64 + icl] = hi;
        g_wlo[(st * 128 + oc) * 64 + icl] = lo;
    }
}

// ---------------- prepass: x transpose + y fold + split; [b,h,w,d][ic] ----------------
__global__ __launch_bounds__(256) void xsplit_kernel(const float* __restrict__ x,
                                                     const float* __restrict__ y) {
    __shared__ float ts[128][33];
    int w_ = blockIdx.x, h = blockIdx.y, b = blockIdx.z;
    int tid = threadIdx.x;
#pragma unroll
    for (int k = 0; k < 16; k++) {
        int e = tid + k * 256;
        int ic = e >> 5, d = e & 31;
        ts[ic][d] = x[((size_t)(b * CC + ic) * SS + h) * 1024 + w_ * SS + d] * y[b * CC + ic];
    }
    __syncthreads();
    size_t nb = (((size_t)(b * SS + h) * SS + w_) * SS) * CC;
#pragma unroll
    for (int k = 0; k < 16; k++) {
        int e = tid + k * 256;
        int d = e >> 7, ic = e & 127;
        float v = ts[ic][d];
        __nv_bfloat16 hi = __float2bfloat16(v);
        __nv_bfloat16 lo = __float2bfloat16(v - __bfloat162float(hi));
        g_xhi[nb + (size_t)d * CC + ic] = hi;
        g_xlo[nb + (size_t)d * CC + ic] = lo;
    }
}

// ---------------- stage loader (cp.async into buf) ----------------
__device__ __forceinline__ void load_stage(uint32_t sb, int tid, int s, int buf,
                                           int b, int h, int w0) {
    int tap = s >> 1, ichalf = s & 1;
    int kd = tap % 3, kw3 = tap / 3;
    int kw = kw3 % 3, kh = kw3 / 3;
    int gh = h + kh - 1;
    bool hok = (unsigned)gh < 32u;
    // A: 2 splits x 128 rows x 8 chunks of 16B
    {
        const char* wh = (const char*)(g_whi + (size_t)s * 128 * 64);
        const char* wl = (const char*)(g_wlo + (size_t)s * 128 * 64);
#pragma unroll
        for (int k = 0; k < 8; k++) {
            int i = tid + k * 256;
            int split = i >> 10, r = i & 1023;
            int row = r >> 3, c = r & 7;
            uint32_t off = (uint32_t)row * 128 + c * 16;
            uint32_t dst = sb + (buf * 2 + split) * A_BYTES + sw128(off);
            const char* src = (split ? wl : wh) + (size_t)row * 128 + c * 16;
            cpasync16(dst, src, 16);
        }
    }
    // B: 2 splits x 256 rows x 8 chunks
    {
#pragma unroll
        for (int k = 0; k < 16; k++) {
            int i = tid + k * 256;
            int split = i >> 11, r = i & 2047;
            int row = r >> 3, c = r & 7;
            int wl_ = row >> 5, d = row & 31;
            int gw = w0 + wl_ + kw - 1, gd = d + kd - 1;
            bool ok = hok && (unsigned)gw < 32u && (unsigned)gd < 32u;
            uint32_t off = (uint32_t)row * 128 + c * 16;
            uint32_t dst = sb + B_OFF + (buf * 2 + split) * B_BYTES + sw128(off);
            const __nv_bfloat16* xb = split ? g_xlo : g_xhi;
            size_t n = ok ? (((size_t)(b * SS + gh) * SS + gw) * SS + gd) : 0;
            const char* src = (const char*)xb + (n * CC + ichalf * 64) * 2 + c * 16;
            cpasync16(dst, src, ok ? 16 : 0);
        }
    }
    CP_COMMIT();
}

// ---------------- main conv: mma.sync implicit GEMM ----------------
__global__ __launch_bounds__(256, 1) void conv_kernel(float* __restrict__ out) {
    extern __shared__ char smem[];
    uint32_t sb = smem_u32(smem);
    int tid = threadIdx.x;
    int wid = tid >> 5, lid = tid & 31;
    int w0 = blockIdx.x * 8;
    int h  = blockIdx.y;
    int b  = blockIdx.z;

    int warp_m = (wid >> 2) * 64;     // 0 or 64 (oc)
    int warp_n = (wid & 3) * 64;      // 0..192 (spatial)

    // per-lane swizzled base offsets for ldmatrix.
    // NOTE: k-step offset must be XORed after swizzle: sw128(off+kk*32)==sw128(off)^(kk*32)
    uint32_t sa[4], sbo[4];
#pragma unroll
    for (int mi = 0; mi < 4; mi++)
        sa[mi] = sw128((uint32_t)(warp_m + mi * 16 + (lid & 15)) * 128 + (lid >> 4) * 16);
#pragma unroll
    for (int nj2 = 0; nj2 < 4; nj2++)
        sbo[nj2] = sw128((uint32_t)(warp_n + nj2 * 16 + (lid & 7) + ((lid >> 4) & 1) * 8) * 128 +
                         ((lid >> 3) & 1) * 16);

    float acc[4][8][4];
#pragma unroll
    for (int mi = 0; mi < 4; mi++)
#pragma unroll
        for (int nj = 0; nj < 8; nj++)
#pragma unroll
            for (int q = 0; q < 4; q++) acc[mi][nj][q] = 0.f;

    load_stage(sb, tid, 0, 0, b, h, w0);

#pragma unroll 1
    for (int s = 1; s <= NSTAGE; s++) {
        if (s < NSTAGE) load_stage(sb, tid, s, s & 1, b, h, w0);
        // compute stage s-1
        int pb = (s - 1) & 1;
        if (s < NSTAGE) { CP_WAIT(1); } else { CP_WAIT(0); }
        __syncthreads();
#pragma unroll 1
        for (int term = 0; term < 3; term++) {
            int asp = (term == 2) ? 1 : 0, bsp = (term == 1) ? 1 : 0;
            uint32_t Ab = sb + (pb * 2 + asp) * A_BYTES;
            uint32_t Bb = sb + B_OFF + (pb * 2 + bsp) * B_BYTES;
#pragma unroll
            for (int kk = 0; kk < 4; kk++) {
                uint32_t kx = (uint32_t)kk * 32;
                uint32_t a[4][4];
#pragma unroll
                for (int mi = 0; mi < 4; mi++)
                    ldsm4(a[mi][0], a[mi][1], a[mi][2], a[mi][3], Ab + (sa[mi] ^ kx));
                uint32_t bf[8][2];
#pragma unroll
                for (int nj2 = 0; nj2 < 4; nj2++)
                    ldsm4(bf[2 * nj2][0], bf[2 * nj2][1], bf[2 * nj2 + 1][0],
                          bf[2 * nj2 + 1][1], Bb + (sbo[nj2] ^ kx));
#pragma unroll
                for (int mi = 0; mi < 4; mi++)
#pragma unroll
                    for (int nj = 0; nj < 8; nj++)
                        mma16816(acc[mi][nj], a[mi], bf[nj]);
            }
        }
        __syncthreads();
    }

    // ---- epilogue: demod scale + float2 stores ----
#pragma unroll
    for (int mi = 0; mi < 4; mi++) {
#pragma unroll
        for (int rr = 0; rr < 2; rr++) {
            int oc = warp_m + mi * 16 + (lid >> 2) + rr * 8;
            float dm = g_demod[b * OCC + oc];
            float* obase = out + ((size_t)(b * OCC + oc) * SS + h) * 1024;
#pragma unroll
            for (int nj = 0; nj < 8; nj++) {
                int n = warp_n + nj * 8 + 2 * (lid & 3);
                int wl_ = n >> 5, d = n & 31;
                float2 v;
                v.x = acc[mi][nj][2 * rr + 0] * dm;
                v.y = acc[mi][nj][2 * rr + 1] * dm;
                *reinterpret_cast<float2*>(obase + (w0 + wl_) * 32 + d) = v;
            }
        }
    }
}

// ---------------------------------------------------------------------------
extern "C" void kernel_launch(void* const* d_in, const int* in_sizes, int n_in,
                              void* d_out, int out_size) {
    const float* x = (const float*)d_in[0];
    const float* y = (const float*)d_in[1];
    const float* w = (const float*)d_in[2];
    float* out = (float*)d_out;

    cudaFuncSetAttribute(conv_kernel, cudaFuncAttributeMaxDynamicSharedMemorySize,
                         SMEM_TOTAL);

    demod_kernel<<<OCC, CC>>>(y, w);
    wsplit_kernel<<<OCC, CC>>>(w);
    xsplit_kernel<<<dim3(SS, SS, BB), 256>>>(x, y);
    conv_kernel<<<dim3(4, SS, BB), 256, SMEM_TOTAL>>>(out);
}

// round 7
// speedup vs baseline: 3.5718x; 1.0414x over previous
#include <cuda_runtime.h>
#include <cuda_bf16.h>
#include <cstdint>
#include <cstddef>

#define BB   4
#define CC   128
#define SS   32
#define OCC  128
#define EPSF 1e-8f

#define NSTAGE 54            // 27 taps * 2 ic-halves
#define A_BYTES 16384        // 128 oc x 128B (64 ic bf16)
#define B_BYTES 32768        // 256 n  x 128B
#define B_OFF   (4 * A_BYTES)
#define CTRL_OFF (B_OFF + 4 * B_BYTES)
#define SMEM_TOTAL (CTRL_OFF + 16)         // 192KB + ctrl
#define NTHR 512
#define NTILE 512
#define GRID 148

__device__ float g_demod[BB * OCC];
__device__ unsigned g_ctr;
__device__ __align__(256) __nv_bfloat16 g_whi[NSTAGE * 128 * 64];
__device__ __align__(256) __nv_bfloat16 g_wlo[NSTAGE * 128 * 64];
__device__ __align__(256) __nv_bfloat16 g_xhi[(size_t)BB * SS * SS * SS * CC];
__device__ __align__(256) __nv_bfloat16 g_xlo[(size_t)BB * SS * SS * SS * CC];

// ---------------- PTX helpers ----------------
__device__ __forceinline__ uint32_t smem_u32(const void* p) {
    uint32_t a;
    asm("{ .reg .u64 t; cvta.to.shared.u64 t, %1; cvt.u32.u64 %0, t; }" : "=r"(a) : "l"(p));
    return a;
}
__device__ __forceinline__ void cpasync16(uint32_t dst, const void* src, int sz) {
    asm volatile("cp.async.cg.shared.global [%0], [%1], 16, %2;"
                 :: "r"(dst), "l"(src), "r"(sz) : "memory");
}
#define CP_COMMIT() asm volatile("cp.async.commit_group;" ::: "memory")
#define CP_WAIT(n)  asm volatile("cp.async.wait_group %0;" :: "n"(n) : "memory")

__device__ __forceinline__ void ldsm4(uint32_t& r0, uint32_t& r1, uint32_t& r2,
                                      uint32_t& r3, uint32_t addr) {
    asm volatile("ldmatrix.sync.aligned.m8n8.x4.shared.b16 {%0,%1,%2,%3}, [%4];"
                 : "=r"(r0), "=r"(r1), "=r"(r2), "=r"(r3) : "r"(addr));
}
__device__ __forceinline__ void mma16816(float* c, const uint32_t* a, const uint32_t* b) {
    asm volatile(
        "mma.sync.aligned.m16n8k16.row.col.f32.bf16.bf16.f32 "
        "{%0,%1,%2,%3}, {%4,%5,%6,%7}, {%8,%9}, {%0,%1,%2,%3};"
        : "+f"(c[0]), "+f"(c[1]), "+f"(c[2]), "+f"(c[3])
        : "r"(a[0]), "r"(a[1]), "r"(a[2]), "r"(a[3]), "r"(b[0]), "r"(b[1]));
}
__device__ __forceinline__ uint32_t sw128(uint32_t off) { return off ^ ((off >> 3) & 0x70); }

// ---------------- prepass: demod (+ counter reset) ----------------
__global__ void demod_kernel(const float* __restrict__ y, const float* __restrict__ w) {
    int oc = blockIdx.x, ic = threadIdx.x;
    if (oc == 0 && ic == 0) g_ctr = GRID;
    const float* wp = w + (oc * CC + ic) * 27;
    float wsum = 0.f;
#pragma unroll
    for (int t = 0; t < 27; t++) { float v = wp[t]; wsum += v * v; }
    __shared__ float red[CC];
    for (int b = 0; b < BB; b++) {
        float yv = y[b * CC + ic];
        red[ic] = wsum * yv * yv;
        __syncthreads();
        for (int s = CC / 2; s > 0; s >>= 1) {
            if (ic < s) red[ic] += red[ic + s];
            __syncthreads();
        }
        if (ic == 0) g_demod[b * OCC + oc] = rsqrtf(red[0] + EPSF);
        __syncthreads();
    }
}

// ---------------- prepass: weight hi/lo split, [stage][oc][icl] ----------------
__global__ void wsplit_kernel(const float* __restrict__ w) {
    int oc = blockIdx.x, ic = threadIdx.x;
    int ichalf = ic >> 6, icl = ic & 63;
#pragma unroll 1
    for (int t = 0; t < 27; t++) {
        float v = w[(oc * CC + ic) * 27 + t];
        __nv_bfloat16 hi = __float2bfloat16(v);
        __nv_bfloat16 lo = __float2bfloat16(v - __bfloat162float(hi));
        int st = t * 2 + ichalf;
        g_whi[(st * 128 + oc) * 64 + icl] = hi;
        g_wlo[(st * 128 + oc) * 64 + icl] = lo;
    }
}

// ---------------- prepass: x transpose + y fold + split; [b,h,w,d][ic] ----------------
__global__ __launch_bounds__(256) void xsplit_kernel(const float* __restrict__ x,
                                                     const float* __restrict__ y) {
    __shared__ float ts[128][33];
    int w_ = blockIdx.x, h = blockIdx.y, b = blockIdx.z;
    int tid = threadIdx.x;
#pragma unroll
    for (int k = 0; k < 16; k++) {
        int e = tid + k * 256;
        int ic = e >> 5, d = e & 31;
        ts[ic][d] = x[((size_t)(b * CC + ic) * SS + h) * 1024 + w_ * SS + d] * y[b * CC + ic];
    }
    __syncthreads();
    size_t nb = (((size_t)(b * SS + h) * SS + w_) * SS) * CC;
#pragma unroll
    for (int k = 0; k < 16; k++) {
        int e = tid + k * 256;
        int d = e >> 7, ic = e & 127;
        float v = ts[ic][d];
        __nv_bfloat16 hi = __float2bfloat16(v);
        __nv_bfloat16 lo = __float2bfloat16(v - __bfloat162float(hi));
        g_xhi[nb + (size_t)d * CC + ic] = hi;
        g_xlo[nb + (size_t)d * CC + ic] = lo;
    }
}

// ---------------- stage loader (cp.async into buf) ----------------
__device__ __forceinline__ void load_stage(uint32_t sb, int tid, int s, int buf,
                                           int b, int h, int w0) {
    int tap = s >> 1, ichalf = s & 1;
    int kd = tap % 3, kw3 = tap / 3;
    int kw = kw3 % 3, kh = kw3 / 3;
    int gh = h + kh - 1;
    bool hok = (unsigned)gh < 32u;
    // A: 2 splits x 128 rows x 8 chunks of 16B = 2048 chunks
    {
        const char* wh = (const char*)(g_whi + (size_t)s * 128 * 64);
        const char* wl = (const char*)(g_wlo + (size_t)s * 128 * 64);
#pragma unroll
        for (int k = 0; k < 4; k++) {
            int i = tid + k * NTHR;
            int split = i >> 10, r = i & 1023;
            int row = r >> 3, c = r & 7;
            uint32_t off = (uint32_t)row * 128 + c * 16;
            uint32_t dst = sb + (buf * 2 + split) * A_BYTES + sw128(off);
            const char* src = (split ? wl : wh) + (size_t)row * 128 + c * 16;
            cpasync16(dst, src, 16);
        }
    }
    // B: 2 splits x 256 rows x 8 chunks = 4096 chunks
    {
#pragma unroll
        for (int k = 0; k < 8; k++) {
            int i = tid + k * NTHR;
            int split = i >> 11, r = i & 2047;
            int row = r >> 3, c = r & 7;
            int wl_ = row >> 5, d = row & 31;
            int gw = w0 + wl_ + kw - 1, gd = d + kd - 1;
            bool ok = hok && (unsigned)gw < 32u && (unsigned)gd < 32u;
            uint32_t off = (uint32_t)row * 128 + c * 16;
            uint32_t dst = sb + B_OFF + (buf * 2 + split) * B_BYTES + sw128(off);
            const __nv_bfloat16* xb = split ? g_xlo : g_xhi;
            size_t n = ok ? (((size_t)(b * SS + gh) * SS + gw) * SS + gd) : 0;
            const char* src = (const char*)xb + (n * CC + ichalf * 64) * 2 + c * 16;
            cpasync16(dst, src, ok ? 16 : 0);
        }
    }
    CP_COMMIT();
}

// ---------------- main conv: persistent mma.sync implicit GEMM ----------------
__global__ __launch_bounds__(NTHR, 1) void conv_kernel(float* __restrict__ out) {
    extern __shared__ char smem[];
    uint32_t sb = smem_u32(smem);
    unsigned* next_tile = (unsigned*)(smem + CTRL_OFF);
    int tid = threadIdx.x;
    int wid = tid >> 5, lid = tid & 31;

    // warp grid: 4m x 4n ; warp tile 32(M) x 64(N)
    int warp_m = (wid & 3) * 32;
    int warp_n = (wid >> 2) * 64;

    // per-lane swizzled ldmatrix base offsets (k-step applied via XOR)
    uint32_t sa[2], sbo[4];
#pragma unroll
    for (int mi = 0; mi < 2; mi++)
        sa[mi] = sw128((uint32_t)(warp_m + mi * 16 + (lid & 15)) * 128 + (lid >> 4) * 16);
#pragma unroll
    for (int nj2 = 0; nj2 < 4; nj2++)
        sbo[nj2] = sw128((uint32_t)(warp_n + nj2 * 16 + (lid & 7) + ((lid >> 4) & 1) * 8) * 128 +
                         ((lid >> 3) & 1) * 16);

    unsigned tile = blockIdx.x;
    while (tile < NTILE) {
        // tile -> (b, h, w-octile)
        int b  = tile >> 7;
        int h  = (tile >> 2) & 31;
        int w0 = (tile & 3) * 8;

        float acc[2][8][4];
#pragma unroll
        for (int mi = 0; mi < 2; mi++)
#pragma unroll
            for (int nj = 0; nj < 8; nj++)
#pragma unroll
                for (int q = 0; q < 4; q++) acc[mi][nj][q] = 0.f;

        load_stage(sb, tid, 0, 0, b, h, w0);

#pragma unroll 1
        for (int s = 1; s <= NSTAGE; s++) {
            if (s < NSTAGE) load_stage(sb, tid, s, s & 1, b, h, w0);
            int pb = (s - 1) & 1;
            if (s < NSTAGE) { CP_WAIT(1); } else { CP_WAIT(0); }
            __syncthreads();
#pragma unroll 1
            for (int term = 0; term < 3; term++) {
                int asp = (term == 2) ? 1 : 0, bsp = (term == 1) ? 1 : 0;
                uint32_t Ab = sb + (pb * 2 + asp) * A_BYTES;
                uint32_t Bb = sb + B_OFF + (pb * 2 + bsp) * B_BYTES;
#pragma unroll
                for (int kk = 0; kk < 4; kk++) {
                    uint32_t kx = (uint32_t)kk * 32;
                    uint32_t a[2][4];
#pragma unroll
                    for (int mi = 0; mi < 2; mi++)
                        ldsm4(a[mi][0], a[mi][1], a[mi][2], a[mi][3], Ab + (sa[mi] ^ kx));
                    uint32_t bf[8][2];
#pragma unroll
                    for (int nj2 = 0; nj2 < 4; nj2++)
                        ldsm4(bf[2 * nj2][0], bf[2 * nj2][1], bf[2 * nj2 + 1][0],
                              bf[2 * nj2 + 1][1], Bb + (sbo[nj2] ^ kx));
#pragma unroll
                    for (int mi = 0; mi < 2; mi++)
#pragma unroll
                        for (int nj = 0; nj < 8; nj++)
                            mma16816(acc[mi][nj], a[mi], bf[nj]);
                }
            }
            __syncthreads();
        }

        // ---- epilogue: demod scale + float2 stores ----
#pragma unroll
        for (int mi = 0; mi < 2; mi++) {
#pragma unroll
            for (int rr = 0; rr < 2; rr++) {
                int oc = warp_m + mi * 16 + (lid >> 2) + rr * 8;
                float dm = g_demod[b * OCC + oc];
                float* obase = out + ((size_t)(b * OCC + oc) * SS + h) * 1024;
#pragma unroll
                for (int nj = 0; nj < 8; nj++) {
                    int n = warp_n + nj * 8 + 2 * (lid & 3);
                    int wl_ = n >> 5, d = n & 31;
                    float2 v;
                    v.x = acc[mi][nj][2 * rr + 0] * dm;
                    v.y = acc[mi][nj][2 * rr + 1] * dm;
                    *reinterpret_cast<float2*>(obase + (w0 + wl_) * 32 + d) = v;
                }
            }
        }

        // ---- next tile (dynamic) ----
        __syncthreads();
        if (tid == 0) *next_tile = atomicAdd(&g_ctr, 1u);
        __syncthreads();
        tile = *next_tile;
    }
}

// ---------------------------------------------------------------------------
extern "C" void kernel_launch(void* const* d_in, const int* in_sizes, int n_in,
                              void* d_out, int out_size) {
    const float* x = (const float*)d_in[0];
    const float* y = (const float*)d_in[1];
    const float* w = (const float*)d_in[2];
    float* out = (float*)d_out;

    cudaFuncSetAttribute(conv_kernel, cudaFuncAttributeMaxDynamicSharedMemorySize,
                         SMEM_TOTAL);

    demod_kernel<<<OCC, CC>>>(y, w);
    wsplit_kernel<<<OCC, CC>>>(w);
    xsplit_kernel<<<dim3(SS, SS, BB), 256>>>(x, y);
    conv_kernel<<<GRID, NTHR, SMEM_TOTAL>>>(out);
}